// round 14
// baseline (speedup 1.0000x reference)
#include <cuda_runtime.h>
#include <cstdint>

// ---------------------------------------------------------------------------
// NeuralMinSumDecoder — banded Tanner graph (A=48271, A^-1=57967 mod 2^16).
// Base b touches checks b..b+5; check c touches bases c-5..c, halves h=0/1.
// One thread per slot, both halves as float2. KK=5 iterations per launch
// (trapezoid halo). Check phase emits RAW ±sel; consumer applies its own
// betas. Beta permutation is PIPELINED ACROSS LAUNCHES: launch g's owned
// threads scatter-load the beta rows for group g+1 and store them coalesced
// into g_betaP; launch g+1 reads them back with 3x LDG.128. Group 0 consumes
// its own betas scattered directly. 2 barriers/iter; syndrome or-reduce
// folded into the mid barrier (deferred one iteration).
// ---------------------------------------------------------------------------

#define MCC   65536
#define NVV   131072
#define TMAXX 30
#define EDG   (NVV * 6)
#define MC6   (MCC * 6)
#define AINV  57967u
#define MMSK  0xFFFFu

#define NB    128                 // owned bases/checks per block
#define KK    5                   // iterations per launch
#define HL    (5 * KK + 5)        // 30 (extra 5 for syndrome halo)
#define HR    (5 * KK)            // 25
#define WW    (NB + HL + HR)      // 183 slots
#define THR   192                 // one thread per slot (warp multiple)
#define GRD   (MCC / NB)          // 512 blocks
#define NLAUNCH (TMAXX / KK)      // 6
#define ST    13                  // smem row stride in float2 (conflict-free)

__device__ __align__(16) float2 g_v2c[2][MC6];  // [buf][c*6+l] = (h0,h1)
// permuted betas, [t][b]: float4 x3 = (h0:l0..l5, h1:l0..l5), 48B per base
__device__ __align__(16) float4 g_betaP[(size_t)TMAXX * MCC * 3];
__device__ float2 g_llr2[MCC];                  // (llr[r], llr[r+M]) by base b
__device__ float2 g_post[MCC];                  // posterior pair by base b
__device__ int    g_synflag[TMAXX];             // 0 => syndrome all-zero at t
// g_synflag: zero-init at load, idempotent across identical replays.

// ---------------------------------------------------------------------------
__global__ __launch_bounds__(THR, 4) void k_fused(
        const float* __restrict__ betas, const float* __restrict__ llr,
        int t0, int rbuf) {
    __shared__ float2 s_msg[WW * ST];            // v2c / raw c2v, in place
    __shared__ unsigned char sp[NB + 6];
    int tid = threadIdx.x;

    // frozen check: one flag per thread, boolean or-reduce (uniform exit)
    int myf = (tid < t0) ? (g_synflag[tid] == 0) : 0;
    if (__syncthreads_or(myf)) return;

    bool act = tid < WW;
    int  s   = act ? tid : WW - 1;
    unsigned B0 = blockIdx.x * NB;
    unsigned c  = (B0 - (unsigned)HL + (unsigned)s) & MMSK;

    unsigned rl[6];
    int eidA[6];                          // edge id, h=0 (argmin tiebreak)
#pragma unroll
    for (int l = 0; l < 6; l++) {
        rl[l]   = (AINV * (c - (unsigned)l)) & MMSK;
        eidA[l] = (int)(rl[l] * 6u + (unsigned)l);
    }

    bool first = (t0 == 0);
    bool pref  = (t0 + KK < TMAXX) && (tid >= HL) && (tid < HL + NB);

    float2 llr2own;
    if (first) {
        // init folded: v2c^0 row straight from llr
        llr2own = make_float2(llr[rl[0]], llr[rl[0] + MCC]);
        if (act) {
            g_llr2[c] = llr2own;                  // for later launches
            s_msg[s * ST + 0] = llr2own;
#pragma unroll
            for (int l = 1; l < 6; l++)
                s_msg[s * ST + l] =
                    make_float2(llr[rl[l]], llr[rl[l] + MCC]);
        }
    } else {
        llr2own = g_llr2[c];
        const float4* gv = (const float4*)&g_v2c[rbuf][c * 6];
        float4 q0 = gv[0], q1 = gv[1], q2 = gv[2];
        if (act) {
            s_msg[s * ST + 0] = make_float2(q0.x, q0.y);
            s_msg[s * ST + 1] = make_float2(q0.z, q0.w);
            s_msg[s * ST + 2] = make_float2(q1.x, q1.y);
            s_msg[s * ST + 3] = make_float2(q1.z, q1.w);
            s_msg[s * ST + 4] = make_float2(q2.x, q2.y);
            s_msg[s * ST + 5] = make_float2(q2.z, q2.w);
        }
    }

    // own betas for iteration t0: (h0 row in ca*, h1 row in cb*)
    float2 ca0, ca1, ca2, cb0, cb1, cb2;
    const float* pr0 = betas + eidA[0];           // scattered own (group 0)
    const float* pr1 = pr0 + MC6;
    const float4* bp =
        g_betaP + ((size_t)t0 * MCC + c) * 3;     // coalesced own (groups >0)
    if (first) {
        ca0 = *(const float2*)(pr0 + 0);
        ca1 = *(const float2*)(pr0 + 2);
        ca2 = *(const float2*)(pr0 + 4);
        cb0 = *(const float2*)(pr1 + 0);
        cb1 = *(const float2*)(pr1 + 2);
        cb2 = *(const float2*)(pr1 + 4);
    } else {
        float4 w0 = bp[0], w1 = bp[1], w2 = bp[2];
        ca0 = make_float2(w0.x, w0.y); ca1 = make_float2(w0.z, w0.w);
        ca2 = make_float2(w1.x, w1.y); cb0 = make_float2(w1.z, w1.w);
        cb1 = make_float2(w2.x, w2.y); cb2 = make_float2(w2.z, w2.w);
    }

    // prefetch pointers for NEXT group's rows (own base), starting t0+KK
    const float* pp0 = betas + (size_t)(t0 + KK) * EDG + eidA[0];
    const float* pp1 = pp0 + MC6;

    float2* gdst = g_v2c[rbuf ^ 1];
    const float INF = __int_as_float(0x7f800000);
    __syncthreads();

    for (int k = 1; k <= KK; k++) {
        // ---- scatter-prefetch next group's beta rows (latency-tolerant) ----
        float2 fa0, fa1, fa2, fb0, fb1, fb2;
        if (pref) {
            fa0 = *(const float2*)(pp0 + 0);
            fa1 = *(const float2*)(pp0 + 2);
            fa2 = *(const float2*)(pp0 + 4);
            fb0 = *(const float2*)(pp1 + 0);
            fb1 = *(const float2*)(pp1 + 2);
            fb2 = *(const float2*)(pp1 + 4);
        }

        // ---- check phase: own row, split h0/h1 top-2 chains ----
        float2 v[6];
#pragma unroll
        for (int l = 0; l < 6; l++) v[l] = s_msg[s * ST + l];

        float mA1 = INF, mA2 = INF, mB1 = INF, mB2 = INF;
        int   eA1 = 0x7fffffff, eB1 = 0x7fffffff;
        unsigned allx = 0u;
#pragma unroll
        for (int l = 0; l < 6; l++) {
            allx ^= __float_as_uint(v[l].x) ^ __float_as_uint(v[l].y);
            float mx = fabsf(v[l].x);
            if (mx < mA1)       { mA2 = mA1; mA1 = mx; eA1 = eidA[l]; }
            else if (mx == mA1) { mA2 = mA1; if (eidA[l] < eA1) eA1 = eidA[l]; }
            else if (mx < mA2)  { mA2 = mx; }
            float my = fabsf(v[l].y);
            int   eB = eidA[l] + MC6;
            if (my < mB1)       { mB2 = mB1; mB1 = my; eB1 = eB; }
            else if (my == mB1) { mB2 = mB1; if (eB < eB1) eB1 = eB; }
            else if (my < mB2)  { mB2 = my; }
        }
        float m1, m2; int e1;
        if (mA1 == mB1)      { m1 = mA1; m2 = mA1; e1 = min(eA1, eB1); }
        else if (mA1 < mB1)  { m1 = mA1; m2 = fminf(mA2, mB1); e1 = eA1; }
        else                 { m1 = mB1; m2 = fminf(mB2, mA1); e1 = eB1; }

        // raw outputs: ±sel (beta applied by the consumer in var phase)
#pragma unroll
        for (int l = 0; l < 6; l++) {
            float selA = (eidA[l]       == e1) ? m2 : m1;
            float selB = (eidA[l] + MC6 == e1) ? m2 : m1;
            unsigned fA = (allx ^ __float_as_uint(v[l].x)) & 0x80000000u;
            unsigned fB = (allx ^ __float_as_uint(v[l].y)) & 0x80000000u;
            float oA = __uint_as_float(__float_as_uint(selA) ^ fA);
            float oB = __uint_as_float(__float_as_uint(selB) ^ fB);
            if (act) s_msg[s * ST + l] = make_float2(oA, oB);
        }

        // ---- mid barrier: publishes raw c2v AND reduces PREVIOUS syndrome --
        int par = 0;
        if (k > 1 && tid < NB)
            par = sp[tid] ^ sp[tid + 1] ^ sp[tid + 2] ^ sp[tid + 3] ^
                  sp[tid + 4] ^ sp[tid + 5];
        int anyodd = __syncthreads_or(par);
        if (k > 1 && anyodd && tid == 0) g_synflag[t0 + k - 2] = 1;

        // ---- variable phase: diagonal reads, own betas in registers ----
        bool actv = tid < WW - 5;
        int  x    = actv ? tid : 0;
        float bx[6] = {ca0.x, ca0.y, ca1.x, ca1.y, ca2.x, ca2.y};
        float by[6] = {cb0.x, cb0.y, cb1.x, cb1.y, cb2.x, cb2.y};
        float2 cv[6];
        float s0 = 0.0f, s1 = 0.0f;
#pragma unroll
        for (int l = 0; l < 6; l++) {
            float2 raw = s_msg[(x + l) * ST + l];
            cv[l] = make_float2(bx[l] * raw.x, by[l] * raw.y);
            s0 += cv[l].x; s1 += cv[l].y;
        }
        float tp0 = llr2own.x + s0;
        float tp1 = llr2own.y + s1;

        // post-consumption advance of own betas for iteration t0+k
        if (k < KK) {
            if (first) {
                pr0 += EDG; pr1 += EDG;
                ca0 = *(const float2*)(pr0 + 0);
                ca1 = *(const float2*)(pr0 + 2);
                ca2 = *(const float2*)(pr0 + 4);
                cb0 = *(const float2*)(pr1 + 0);
                cb1 = *(const float2*)(pr1 + 2);
                cb2 = *(const float2*)(pr1 + 4);
            } else {
                bp += (size_t)MCC * 3;
                float4 w0 = bp[0], w1 = bp[1], w2 = bp[2];
                ca0 = make_float2(w0.x, w0.y); ca1 = make_float2(w0.z, w0.w);
                ca2 = make_float2(w1.x, w1.y); cb0 = make_float2(w1.z, w1.w);
                cb1 = make_float2(w2.x, w2.y); cb2 = make_float2(w2.z, w2.w);
            }
        }

        if (k < KK) {
            if (actv) {
#pragma unroll
                for (int l = 0; l < 6; l++)
                    s_msg[(x + l) * ST + l] =
                        make_float2(tp0 - cv[l].x, tp1 - cv[l].y);
            }
        } else if (tid >= HL && tid < HL + NB) {      // owned writeback
#pragma unroll
            for (int l = 0; l < 6; l++)
                gdst[(int)(((c + (unsigned)l) & MMSK) * 6u + (unsigned)l)] =
                    make_float2(tp0 - cv[l].x, tp1 - cv[l].y);
            g_post[c] = make_float2(tp0, tp1);
        }
        if (tid >= HL - 5 && tid < HL + NB)
            sp[tid - (HL - 5)] =
                (unsigned char)(((tp0 < 0.0f) ? 1 : 0) ^ ((tp1 < 0.0f) ? 1 : 0));
        __syncthreads();                              // end-of-iter barrier

        // ---- store prefetched rows coalesced for the next launch ----
        if (pref) {
            float4* dst = g_betaP + ((size_t)(t0 + KK + k - 1) * MCC + c) * 3;
            dst[0] = make_float4(fa0.x, fa0.y, fa1.x, fa1.y);
            dst[1] = make_float4(fa2.x, fa2.y, fb0.x, fb0.y);
            dst[2] = make_float4(fb1.x, fb1.y, fb2.x, fb2.y);
            pp0 += EDG; pp1 += EDG;
        }
    }

    // trailing syndrome reduce for iteration t0+KK-1
    int par = 0;
    if (tid < NB)
        par = sp[tid] ^ sp[tid + 1] ^ sp[tid + 2] ^ sp[tid + 3] ^
              sp[tid + 4] ^ sp[tid + 5];
    int anyodd = __syncthreads_or(par);
    if (anyodd && tid == 0) g_synflag[t0 + KK - 1] = 1;   // benign race
}

// ---------------------------------------------------------------------------
__global__ void k_out(float* __restrict__ out, int out_size) {
    unsigned b = blockIdx.x * blockDim.x + threadIdx.x;   // base 0..MC-1
    float2 P = g_post[b];
    unsigned r = (AINV * b) & MMSK;

    if ((int)r < out_size)               out[r]             = (P.x < 0.0f) ? 1.0f : 0.0f;
    if ((int)(r + MCC) < out_size)       out[r + MCC]       = (P.y < 0.0f) ? 1.0f : 0.0f;
    if ((int)(NVV + r) < out_size)       out[NVV + r]       = P.x;
    if ((int)(NVV + r + MCC) < out_size) out[NVV + r + MCC] = P.y;

    if (b == 0 && 2 * NVV < out_size) {
        int iters = TMAXX;
        for (int tt = 0; tt < TMAXX; tt++)
            if (g_synflag[tt] == 0) { iters = tt + 1; break; }
        out[2 * NVV] = (float)iters;
    }
}

// ---------------------------------------------------------------------------
extern "C" void kernel_launch(void* const* d_in, const int* in_sizes, int n_in,
                              void* d_out, int out_size) {
    const float* llr   = (const float*)d_in[0];
    const float* betas = (const float*)d_in[1];
    (void)in_sizes; (void)n_in;

    for (int g = 0; g < NLAUNCH; g++)
        k_fused<<<GRD, THR>>>(betas, llr, g * KK, g & 1);
    k_out<<<MCC / 256, 256>>>((float*)d_out, out_size);
}

// round 15
// speedup vs baseline: 1.3041x; 1.3041x over previous
#include <cuda_runtime.h>
#include <cstdint>

// ---------------------------------------------------------------------------
// NeuralMinSumDecoder — banded Tanner graph (A=48271, A^-1=57967 mod 2^16).
// Base b touches checks b..b+5; check c touches bases c-5..c, halves h=0/1.
// PERSISTENT single kernel: 6 phases x KK=5 iterations, software grid barrier
// between phases (all 512 blocks co-resident by __launch_bounds__(192,4):
// 512 <= 4*152). One thread per slot, both halves as float2; 197-row valid
// window -> no predicates. Check emits RAW ±sel; consumer applies its own
// register-resident betas (scattered 24B rows, loaded once per iteration,
// next phase's first row prefetched across the barrier). Outputs written
// directly each phase (last active phase wins). Barrier counter reset by a
// captured cudaMemsetAsync; g_synflag zero-init + idempotent across replays.
// ---------------------------------------------------------------------------

#define MCC   65536
#define NVV   131072
#define TMAXX 30
#define EDG   (NVV * 6)
#define MC6   (MCC * 6)
#define AINV  57967u
#define MMSK  0xFFFFu

#define NB    128                 // owned bases/checks per block
#define KK    5                   // iterations per phase
#define PH    (TMAXX / KK)        // 6 phases
#define HL    30                  // left halo (5*KK + 5 for syndrome)
#define THR   192                 // threads == check rows computed
#define ROWS  197                 // valid window rows (192 + 5 extra)
#define GRD   (MCC / NB)          // 512 blocks (co-resident)
#define ST    13                  // smem row stride in float2 (conflict-free)

__device__ __align__(16) float2 g_v2c[MC6];     // [c*6+l] = (h0,h1)
__device__ int      g_synflag[TMAXX];           // 0 => syndrome all-zero at t
__device__ unsigned g_bar;                      // grid barrier counter

// ---------------------------------------------------------------------------
__device__ __forceinline__ void gsync(unsigned target) {
    __syncthreads();
    if (threadIdx.x == 0) {
        __threadfence();
        atomicAdd(&g_bar, 1u);
        while (*((volatile unsigned*)&g_bar) < target * (unsigned)GRD) { }
        __threadfence();
    }
    __syncthreads();
}

// ---------------------------------------------------------------------------
__global__ __launch_bounds__(THR, 4) void k_all(
        const float* __restrict__ betas, const float* __restrict__ llr,
        float* __restrict__ out, int out_size) {
    __shared__ float2 s_msg[(ROWS + 5) * ST];    // v2c / raw c2v, in place
    __shared__ unsigned char sp[NB + 6];
    int tid = threadIdx.x;
    unsigned B0 = blockIdx.x * NB;
    unsigned c  = (B0 - (unsigned)HL + (unsigned)tid) & MMSK;
    unsigned cx = (c + 192u) & MMSK;             // extra row for tid < 5

    unsigned r0 = (AINV * c) & MMSK;             // own base's variable index
    int eidA[6];                                 // edge id, h=0
#pragma unroll
    for (int l = 0; l < 6; l++)
        eidA[l] = (int)((((AINV * (c - (unsigned)l)) & MMSK)) * 6u +
                        (unsigned)l);
    float2 llr2own = make_float2(llr[r0], llr[r0 + MCC]);
    bool owned = (tid >= HL) && (tid < HL + NB);

    // own betas for iteration 0 (two contiguous 24B rows)
    const float* pr0 = betas + eidA[0];
    const float* pr1 = pr0 + MC6;
    float2 ca0 = *(const float2*)(pr0 + 0);
    float2 ca1 = *(const float2*)(pr0 + 2);
    float2 ca2 = *(const float2*)(pr0 + 4);
    float2 cb0 = *(const float2*)(pr1 + 0);
    float2 cb1 = *(const float2*)(pr1 + 2);
    float2 cb2 = *(const float2*)(pr1 + 4);
    const float INF = __int_as_float(0x7f800000);

    for (int g = 0; g < PH; g++) {
        int t0 = g * KK;
        int myf = (tid < t0) ? (g_synflag[tid] == 0) : 0;
        int frozen = __syncthreads_or(myf);
        if (!frozen) {
            // ---- (re)load the 197-row v2c window ----
            if (g == 0) {
                s_msg[tid * ST + 0] = llr2own;
#pragma unroll
                for (int l = 1; l < 6; l++) {
                    unsigned rl = (AINV * (c - (unsigned)l)) & MMSK;
                    s_msg[tid * ST + l] = make_float2(llr[rl], llr[rl + MCC]);
                }
                if (tid < 5) {
#pragma unroll
                    for (int l = 0; l < 6; l++) {
                        unsigned rx = (AINV * (cx - (unsigned)l)) & MMSK;
                        s_msg[(192 + tid) * ST + l] =
                            make_float2(llr[rx], llr[rx + MCC]);
                    }
                }
            } else {
                const float4* gv = (const float4*)&g_v2c[c * 6];
                float4 q0 = gv[0], q1 = gv[1], q2 = gv[2];
                s_msg[tid * ST + 0] = make_float2(q0.x, q0.y);
                s_msg[tid * ST + 1] = make_float2(q0.z, q0.w);
                s_msg[tid * ST + 2] = make_float2(q1.x, q1.y);
                s_msg[tid * ST + 3] = make_float2(q1.z, q1.w);
                s_msg[tid * ST + 4] = make_float2(q2.x, q2.y);
                s_msg[tid * ST + 5] = make_float2(q2.z, q2.w);
                if (tid < 5) {
                    const float4* gx = (const float4*)&g_v2c[cx * 6];
                    float4 x0 = gx[0], x1 = gx[1], x2 = gx[2];
                    float2* row = &s_msg[(192 + tid) * ST];
                    row[0] = make_float2(x0.x, x0.y);
                    row[1] = make_float2(x0.z, x0.w);
                    row[2] = make_float2(x1.x, x1.y);
                    row[3] = make_float2(x1.z, x1.w);
                    row[4] = make_float2(x2.x, x2.y);
                    row[5] = make_float2(x2.z, x2.w);
                }
            }
            __syncthreads();

            for (int k = 1; k <= KK; k++) {
                // ---- check phase: own row, split h0/h1 top-2 chains ----
                float2 v[6];
#pragma unroll
                for (int l = 0; l < 6; l++) v[l] = s_msg[tid * ST + l];

                float mA1 = INF, mA2 = INF, mB1 = INF, mB2 = INF;
                int   eA1 = 0x7fffffff, eB1 = 0x7fffffff;
                unsigned allx = 0u;
#pragma unroll
                for (int l = 0; l < 6; l++) {
                    allx ^= __float_as_uint(v[l].x) ^ __float_as_uint(v[l].y);
                    float mx = fabsf(v[l].x);
                    if (mx < mA1)       { mA2 = mA1; mA1 = mx; eA1 = eidA[l]; }
                    else if (mx == mA1) { mA2 = mA1;
                                          if (eidA[l] < eA1) eA1 = eidA[l]; }
                    else if (mx < mA2)  { mA2 = mx; }
                    float my = fabsf(v[l].y);
                    int   eB = eidA[l] + MC6;
                    if (my < mB1)       { mB2 = mB1; mB1 = my; eB1 = eB; }
                    else if (my == mB1) { mB2 = mB1; if (eB < eB1) eB1 = eB; }
                    else if (my < mB2)  { mB2 = my; }
                }
                float m1, m2; int e1;
                if (mA1 == mB1)     { m1 = mA1; m2 = mA1; e1 = min(eA1, eB1); }
                else if (mA1 < mB1) { m1 = mA1; m2 = fminf(mA2, mB1); e1 = eA1; }
                else                { m1 = mB1; m2 = fminf(mB2, mA1); e1 = eB1; }

#pragma unroll
                for (int l = 0; l < 6; l++) {
                    float selA = (eidA[l]       == e1) ? m2 : m1;
                    float selB = (eidA[l] + MC6 == e1) ? m2 : m1;
                    unsigned fA = (allx ^ __float_as_uint(v[l].x)) & 0x80000000u;
                    unsigned fB = (allx ^ __float_as_uint(v[l].y)) & 0x80000000u;
                    s_msg[tid * ST + l] = make_float2(
                        __uint_as_float(__float_as_uint(selA) ^ fA),
                        __uint_as_float(__float_as_uint(selB) ^ fB));
                }

                // ---- mid barrier: publish c2v + reduce PREVIOUS syndrome ---
                int par = 0;
                if (k > 1 && tid < NB)
                    par = sp[tid] ^ sp[tid + 1] ^ sp[tid + 2] ^ sp[tid + 3] ^
                          sp[tid + 4] ^ sp[tid + 5];
                int anyodd = __syncthreads_or(par);
                if (k > 1 && anyodd && tid == 0) g_synflag[t0 + k - 2] = 1;

                // ---- variable phase: diagonal reads, own betas ----
                float bx[6] = {ca0.x, ca0.y, ca1.x, ca1.y, ca2.x, ca2.y};
                float by[6] = {cb0.x, cb0.y, cb1.x, cb1.y, cb2.x, cb2.y};
                float2 cv[6];
                float s0 = 0.0f, s1 = 0.0f;
#pragma unroll
                for (int l = 0; l < 6; l++) {
                    float2 raw = s_msg[(tid + l) * ST + l];
                    cv[l] = make_float2(bx[l] * raw.x, by[l] * raw.y);
                    s0 += cv[l].x; s1 += cv[l].y;
                }
                float tp0 = llr2own.x + s0;
                float tp1 = llr2own.y + s1;

                // post-consumption advance (rolls across the grid barrier)
                if (t0 + k < TMAXX) {
                    pr0 += EDG; pr1 += EDG;
                    ca0 = *(const float2*)(pr0 + 0);
                    ca1 = *(const float2*)(pr0 + 2);
                    ca2 = *(const float2*)(pr0 + 4);
                    cb0 = *(const float2*)(pr1 + 0);
                    cb1 = *(const float2*)(pr1 + 2);
                    cb2 = *(const float2*)(pr1 + 4);
                }

                if (k < KK) {
#pragma unroll
                    for (int l = 0; l < 6; l++)
                        s_msg[(tid + l) * ST + l] =
                            make_float2(tp0 - cv[l].x, tp1 - cv[l].y);
                } else if (owned) {
#pragma unroll
                    for (int l = 0; l < 6; l++)
                        g_v2c[(int)(((c + (unsigned)l) & MMSK) * 6u +
                                    (unsigned)l)] =
                            make_float2(tp0 - cv[l].x, tp1 - cv[l].y);
                    // direct output (last active phase wins)
                    if ((int)r0 < out_size)
                        out[r0] = (tp0 < 0.0f) ? 1.0f : 0.0f;
                    if ((int)(r0 + MCC) < out_size)
                        out[r0 + MCC] = (tp1 < 0.0f) ? 1.0f : 0.0f;
                    if ((int)(NVV + r0) < out_size)
                        out[NVV + r0] = tp0;
                    if ((int)(NVV + r0 + MCC) < out_size)
                        out[NVV + r0 + MCC] = tp1;
                }
                if (tid >= HL - 5 && tid < HL + NB)
                    sp[tid - (HL - 5)] = (unsigned char)(
                        ((tp0 < 0.0f) ? 1 : 0) ^ ((tp1 < 0.0f) ? 1 : 0));
                __syncthreads();                      // end-of-iter barrier
            }

            // trailing syndrome reduce for iteration t0+KK-1
            int par = 0;
            if (tid < NB)
                par = sp[tid] ^ sp[tid + 1] ^ sp[tid + 2] ^ sp[tid + 3] ^
                      sp[tid + 4] ^ sp[tid + 5];
            int anyodd = __syncthreads_or(par);
            if (anyodd && tid == 0) g_synflag[t0 + KK - 1] = 1;
        }
        gsync((unsigned)(g + 1));                     // grid barrier
    }

    // iters (all flags visible after the final grid barrier)
    if (blockIdx.x == 0 && tid == 0 && 2 * NVV < out_size) {
        int iters = TMAXX;
        for (int tt = 0; tt < TMAXX; tt++)
            if (g_synflag[tt] == 0) { iters = tt + 1; break; }
        out[2 * NVV] = (float)iters;
    }
}

// ---------------------------------------------------------------------------
extern "C" void kernel_launch(void* const* d_in, const int* in_sizes, int n_in,
                              void* d_out, int out_size) {
    const float* llr   = (const float*)d_in[0];
    const float* betas = (const float*)d_in[1];
    (void)in_sizes; (void)n_in;

    void* bar_addr = nullptr;
    cudaGetSymbolAddress(&bar_addr, g_bar);
    cudaMemsetAsync(bar_addr, 0, sizeof(unsigned));   // capturable reset
    k_all<<<GRD, THR>>>(betas, llr, (float*)d_out, out_size);
}

// round 16
// speedup vs baseline: 1.3611x; 1.0438x over previous
#include <cuda_runtime.h>
#include <cstdint>

// ---------------------------------------------------------------------------
// NeuralMinSumDecoder — banded Tanner graph (A=48271, A^-1=57967 mod 2^16).
// Base b touches checks b..b+5; check c touches bases c-5..c, halves h=0/1.
// KK=5 iterations per launch, 6 launches. WARP-AUTONOMOUS iterations:
// 7 warps; warp w owns var-slots [s_w, s_w+n_w) and computes check messages
// for [s_w, s_w+n_w+5) in REGISTERS (5-slot redundant halo); the diagonal
// c2v exchange is __shfl_sync(lane+l) — no smem c2v, no mid barrier.
// v2c ping-pongs between two smem buffers; the single end-of-iteration
// barrier is the __syncthreads_or syndrome reduce (sp double-buffered,
// deferred one iteration). Betas consumed by their owner (raw ±sel from
// check, beta applied at var — bitwise identical).
// ---------------------------------------------------------------------------

#define MCC   65536
#define NVV   131072
#define TMAXX 30
#define EDG   (NVV * 6)
#define MC6   (MCC * 6)
#define AINV  57967u
#define MMSK  0xFFFFu

#define NB    128                 // owned bases/checks per block
#define KK    5                   // iterations per launch
#define HL    30                  // left halo (5*KK + 5 for syndrome)
#define WW    183                 // window rows (NB + 30 + 25)
#define NVAR  178                 // var-updated rows (WW - 5)
#define THR   224                 // 7 warps
#define GRD   (MCC / NB)          // 512 blocks (<= 4/SM * 152 = single wave)
#define NLAUNCH (TMAXX / KK)      // 6
#define ST    13                  // smem row stride in float2 (conflict-free)

__device__ __align__(16) float2 g_v2c[2][MC6];  // [buf][c*6+l] = (h0,h1)
__device__ float2 g_llr2[MCC];                  // (llr[r], llr[r+M]) by base b
__device__ float2 g_post[MCC];                  // posterior pair by base b
__device__ int    g_synflag[TMAXX];             // 0 => syndrome all-zero at t
// g_synflag: zero-init at load, idempotent across identical replays.

// ---------------------------------------------------------------------------
__global__ __launch_bounds__(THR, 4) void k_fused(
        const float* __restrict__ betas, const float* __restrict__ llr,
        int t0, int rbuf) {
    __shared__ float2 s_msg[2][WW * ST];         // v2c ping-pong buffers
    __shared__ unsigned char sp[2][NB + 8];      // parity bits, slots 25..157
    int tid  = threadIdx.x;
    int w    = tid >> 5;
    int lane = tid & 31;

    // frozen check: one flag per thread, boolean or-reduce (uniform exit)
    int myf = (tid < t0) ? (g_synflag[tid] == 0) : 0;
    if (__syncthreads_or(myf)) return;

    int sw = (w < 3) ? 26 * w : 78 + 25 * (w - 3);   // 0,26,52,78,103,128,153
    int nw = (w < 3) ? 26 : 25;
    bool chk  = lane < nw + 5;
    bool vard = lane < nw;
    int  s    = sw + (chk ? lane : 0);           // clamped slot
    unsigned B0 = blockIdx.x * NB;
    unsigned c  = (B0 - (unsigned)HL + (unsigned)s) & MMSK;

    unsigned r0 = (AINV * c) & MMSK;
    int eidA[6];                                 // edge id, h=0
#pragma unroll
    for (int l = 0; l < 6; l++)
        eidA[l] = (int)((((AINV * (c - (unsigned)l)) & MMSK)) * 6u +
                        (unsigned)l);

    // ---- initial window load into buffer 0 (linear by tid) ----
    float2 llr2own;
    if (t0 == 0) {
        llr2own = make_float2(llr[r0], llr[r0 + MCC]);
        if (chk) g_llr2[c] = llr2own;            // duplicates benign
        for (int i = tid; i < WW; i += THR) {
            unsigned ci = (B0 - (unsigned)HL + (unsigned)i) & MMSK;
#pragma unroll
            for (int l = 0; l < 6; l++) {
                unsigned rl = (AINV * (ci - (unsigned)l)) & MMSK;
                s_msg[0][i * ST + l] = make_float2(llr[rl], llr[rl + MCC]);
            }
        }
    } else {
        llr2own = g_llr2[c];
        for (int i = tid; i < WW; i += THR) {
            unsigned ci = (B0 - (unsigned)HL + (unsigned)i) & MMSK;
            const float4* gv = (const float4*)&g_v2c[rbuf][ci * 6];
            float4 q0 = gv[0], q1 = gv[1], q2 = gv[2];
            float2* row = &s_msg[0][i * ST];
            row[0] = make_float2(q0.x, q0.y);
            row[1] = make_float2(q0.z, q0.w);
            row[2] = make_float2(q1.x, q1.y);
            row[3] = make_float2(q1.z, q1.w);
            row[4] = make_float2(q2.x, q2.y);
            row[5] = make_float2(q2.z, q2.w);
        }
    }

    // own betas for iteration t0 (two contiguous 24B rows of own base)
    const float* pr0 = betas + (size_t)t0 * EDG + (int)(r0 * 6u);
    const float* pr1 = pr0 + MC6;
    float2 ca0 = *(const float2*)(pr0 + 0);
    float2 ca1 = *(const float2*)(pr0 + 2);
    float2 ca2 = *(const float2*)(pr0 + 4);
    float2 cb0 = *(const float2*)(pr1 + 0);
    float2 cb1 = *(const float2*)(pr1 + 2);
    float2 cb2 = *(const float2*)(pr1 + 4);
    float2* gdst = g_v2c[rbuf ^ 1];
    const float INF = __int_as_float(0x7f800000);
    bool owned = vard && (s >= HL) && (s < HL + NB);
    bool spw   = vard && (s >= HL - 5) && (s < HL + NB);
    __syncthreads();

    for (int k = 1; k <= KK; k++) {
        const int cur = (k - 1) & 1, nxt = k & 1;
        const float2* mcur = s_msg[cur];
        float2*       mnxt = s_msg[nxt];

        // ---- check phase (registers only): own row, split h0/h1 top-2 ----
        float2 v[6];
#pragma unroll
        for (int l = 0; l < 6; l++) v[l] = mcur[s * ST + l];

        float mA1 = INF, mA2 = INF, mB1 = INF, mB2 = INF;
        int   eA1 = 0x7fffffff, eB1 = 0x7fffffff;
        unsigned allx = 0u;
#pragma unroll
        for (int l = 0; l < 6; l++) {
            allx ^= __float_as_uint(v[l].x) ^ __float_as_uint(v[l].y);
            float mx = fabsf(v[l].x);
            if (mx < mA1)       { mA2 = mA1; mA1 = mx; eA1 = eidA[l]; }
            else if (mx == mA1) { mA2 = mA1; if (eidA[l] < eA1) eA1 = eidA[l]; }
            else if (mx < mA2)  { mA2 = mx; }
            float my = fabsf(v[l].y);
            int   eB = eidA[l] + MC6;
            if (my < mB1)       { mB2 = mB1; mB1 = my; eB1 = eB; }
            else if (my == mB1) { mB2 = mB1; if (eB < eB1) eB1 = eB; }
            else if (my < mB2)  { mB2 = my; }
        }
        float m1, m2; int e1;
        if (mA1 == mB1)     { m1 = mA1; m2 = mA1; e1 = min(eA1, eB1); }
        else if (mA1 < mB1) { m1 = mA1; m2 = fminf(mA2, mB1); e1 = eA1; }
        else                { m1 = mB1; m2 = fminf(mB2, mA1); e1 = eB1; }

        float cregx[6], cregy[6];                // raw ±sel, in registers
#pragma unroll
        for (int l = 0; l < 6; l++) {
            float selA = (eidA[l]       == e1) ? m2 : m1;
            float selB = (eidA[l] + MC6 == e1) ? m2 : m1;
            unsigned fA = (allx ^ __float_as_uint(v[l].x)) & 0x80000000u;
            unsigned fB = (allx ^ __float_as_uint(v[l].y)) & 0x80000000u;
            cregx[l] = __uint_as_float(__float_as_uint(selA) ^ fA);
            cregy[l] = __uint_as_float(__float_as_uint(selB) ^ fB);
        }

        // parity of PREVIOUS iteration (sp[cur], stable this iteration)
        int par = 0;
        if (k > 1 && tid < NB) {
            const unsigned char* q = sp[cur];
            par = q[tid] ^ q[tid + 1] ^ q[tid + 2] ^ q[tid + 3] ^
                  q[tid + 4] ^ q[tid + 5];
        }

        // ---- var phase: diagonal via warp shuffle (no smem c2v) ----
        float bx[6] = {ca0.x, ca0.y, ca1.x, ca1.y, ca2.x, ca2.y};
        float by[6] = {cb0.x, cb0.y, cb1.x, cb1.y, cb2.x, cb2.y};
        float2 cv[6];
        float s0 = 0.0f, s1 = 0.0f;
#pragma unroll
        for (int l = 0; l < 6; l++) {
            float rx = __shfl_sync(0xffffffffu, cregx[l], lane + l);
            float ry = __shfl_sync(0xffffffffu, cregy[l], lane + l);
            cv[l] = make_float2(bx[l] * rx, by[l] * ry);
            s0 += cv[l].x; s1 += cv[l].y;
        }
        float tp0 = llr2own.x + s0;
        float tp1 = llr2own.y + s1;

        // post-consumption advance of own betas for iteration t0+k
        if (t0 + k < TMAXX) {
            pr0 += EDG; pr1 += EDG;
            ca0 = *(const float2*)(pr0 + 0);
            ca1 = *(const float2*)(pr0 + 2);
            ca2 = *(const float2*)(pr0 + 4);
            cb0 = *(const float2*)(pr1 + 0);
            cb1 = *(const float2*)(pr1 + 2);
            cb2 = *(const float2*)(pr1 + 4);
        }

        if (k < KK) {
            if (vard) {
#pragma unroll
                for (int l = 0; l < 6; l++)
                    mnxt[(s + l) * ST + l] =
                        make_float2(tp0 - cv[l].x, tp1 - cv[l].y);
            }
        } else if (owned) {                       // last iter: global writeback
#pragma unroll
            for (int l = 0; l < 6; l++)
                gdst[(int)(((c + (unsigned)l) & MMSK) * 6u + (unsigned)l)] =
                    make_float2(tp0 - cv[l].x, tp1 - cv[l].y);
            g_post[c] = make_float2(tp0, tp1);
        }
        if (spw)
            sp[nxt][s - (HL - 5)] = (unsigned char)(
                ((tp0 < 0.0f) ? 1 : 0) ^ ((tp1 < 0.0f) ? 1 : 0));

        // ---- single end-of-iteration barrier == syndrome or-reduce ----
        int anyodd = __syncthreads_or(par);
        if (k > 1 && anyodd && tid == 0) g_synflag[t0 + k - 2] = 1;
    }

    // trailing reduce for iteration t0+KK-1 (sp[KK&1])
    int par = 0;
    if (tid < NB) {
        const unsigned char* q = sp[KK & 1];
        par = q[tid] ^ q[tid + 1] ^ q[tid + 2] ^ q[tid + 3] ^
              q[tid + 4] ^ q[tid + 5];
    }
    int anyodd = __syncthreads_or(par);
    if (anyodd && tid == 0) g_synflag[t0 + KK - 1] = 1;   // benign race
}

// ---------------------------------------------------------------------------
__global__ void k_out(float* __restrict__ out, int out_size) {
    unsigned b = blockIdx.x * blockDim.x + threadIdx.x;   // base 0..MC-1
    float2 P = g_post[b];
    unsigned r = (AINV * b) & MMSK;

    if ((int)r < out_size)               out[r]             = (P.x < 0.0f) ? 1.0f : 0.0f;
    if ((int)(r + MCC) < out_size)       out[r + MCC]       = (P.y < 0.0f) ? 1.0f : 0.0f;
    if ((int)(NVV + r) < out_size)       out[NVV + r]       = P.x;
    if ((int)(NVV + r + MCC) < out_size) out[NVV + r + MCC] = P.y;

    if (b == 0 && 2 * NVV < out_size) {
        int iters = TMAXX;
        for (int tt = 0; tt < TMAXX; tt++)
            if (g_synflag[tt] == 0) { iters = tt + 1; break; }
        out[2 * NVV] = (float)iters;
    }
}

// ---------------------------------------------------------------------------
extern "C" void kernel_launch(void* const* d_in, const int* in_sizes, int n_in,
                              void* d_out, int out_size) {
    const float* llr   = (const float*)d_in[0];
    const float* betas = (const float*)d_in[1];
    (void)in_sizes; (void)n_in;

    for (int g = 0; g < NLAUNCH; g++)
        k_fused<<<GRD, THR>>>(betas, llr, g * KK, g & 1);
    k_out<<<MCC / 256, 256>>>((float*)d_out, out_size);
}